// round 1
// baseline (speedup 1.0000x reference)
#include <cuda_runtime.h>
#include <cuda_bf16.h>
#include <cstdint>

// Problem constants
#define BATCH 8
#define FIN   64
#define NPTS  4096
#define FOUT  64
#define KNN   20

// Scratch (device globals: no allocations allowed)
__device__ float g_Yt[BATCH * NPTS * FOUT];   // Y^T: [b][n][o]  (W2 . x_n)
__device__ float g_Ct[BATCH * NPTS * FOUT];   // C^T: [b][n][o]  ((W1-W2) . x_n + b)
__device__ float g_sq[BATCH * NPTS];          // ||x_n||^2
__device__ int   g_idx[BATCH * NPTS * KNN];   // top-k neighbor indices (batch-local)

// ---------------------------------------------------------------------------
// Kernel 1: per-point features: Yt, Ct, sq
// grid (32, 8), 128 threads; block handles 128 points of one batch
// ---------------------------------------------------------------------------
__global__ __launch_bounds__(128) void k1_features(
    const float* __restrict__ x, const float* __restrict__ W,
    const float* __restrict__ bvec)
{
    __shared__ float W2s[64][64];   // [f][o]
    __shared__ float Wds[64][64];   // [f][o]  (W1 - W2)
    __shared__ float bs[64];

    const int bb  = blockIdx.y;
    const int n0  = blockIdx.x * 128;
    const int tid = threadIdx.x;

    for (int idx = tid; idx < 64 * 64; idx += 128) {
        int f = idx >> 6, o = idx & 63;
        float w1 = W[o * 128 + f];
        float w2 = W[o * 128 + 64 + f];
        W2s[f][o] = w2;
        Wds[f][o] = w1 - w2;
    }
    if (tid < 64) bs[tid] = bvec[tid];
    __syncthreads();

    const float* xb = x + (size_t)bb * FIN * NPTS;
    const int n = n0 + tid;

    float xr[64];
#pragma unroll
    for (int f = 0; f < 64; ++f) xr[f] = xb[f * NPTS + n];

    float sq = 0.f;
#pragma unroll
    for (int f = 0; f < 64; ++f) sq = fmaf(xr[f], xr[f], sq);
    g_sq[bb * NPTS + n] = sq;

    const size_t base = ((size_t)(bb * NPTS + n)) * 64;

#pragma unroll 1
    for (int half = 0; half < 2; ++half) {
        float ya[32], ca[32];
#pragma unroll
        for (int oo = 0; oo < 32; ++oo) { ya[oo] = 0.f; ca[oo] = bs[half * 32 + oo]; }

#pragma unroll 4
        for (int f = 0; f < 64; ++f) {
            float xf = xr[f];
#pragma unroll
            for (int oo = 0; oo < 32; oo += 4) {
                float4 w2 = *(const float4*)&W2s[f][half * 32 + oo];
                float4 wd = *(const float4*)&Wds[f][half * 32 + oo];
                ya[oo + 0] = fmaf(w2.x, xf, ya[oo + 0]);
                ya[oo + 1] = fmaf(w2.y, xf, ya[oo + 1]);
                ya[oo + 2] = fmaf(w2.z, xf, ya[oo + 2]);
                ya[oo + 3] = fmaf(w2.w, xf, ya[oo + 3]);
                ca[oo + 0] = fmaf(wd.x, xf, ca[oo + 0]);
                ca[oo + 1] = fmaf(wd.y, xf, ca[oo + 1]);
                ca[oo + 2] = fmaf(wd.z, xf, ca[oo + 2]);
                ca[oo + 3] = fmaf(wd.w, xf, ca[oo + 3]);
            }
        }
        float4* Yp = (float4*)(g_Yt + base + half * 32);
        float4* Cp = (float4*)(g_Ct + base + half * 32);
#pragma unroll
        for (int q = 0; q < 8; ++q) {
            Yp[q] = make_float4(ya[4 * q], ya[4 * q + 1], ya[4 * q + 2], ya[4 * q + 3]);
            Cp[q] = make_float4(ca[4 * q], ca[4 * q + 1], ca[4 * q + 2], ca[4 * q + 3]);
        }
    }
}

// ---------------------------------------------------------------------------
// Kernel 2: fused distance GEMM (fma.rn.f32x2) + streaming top-20
// grid 128 (= B * N/256), 256 threads; each thread owns one query row n.
// Smem: As[64][256] (query features, k-major), Bs[64][64] (candidate tile),
//       Ds[256][65] (dot tile, padded), sqs[64]
// ---------------------------------------------------------------------------
#define K2_AS (64 * 256)
#define K2_BS (64 * 64)
#define K2_DS (256 * 65)
#define K2_SMEM_FLOATS (K2_AS + K2_BS + K2_DS + 64)
#define K2_SMEM_BYTES (K2_SMEM_FLOATS * 4)

__global__ __launch_bounds__(256, 1) void k2_knn(const float* __restrict__ x)
{
    extern __shared__ float sm[];
    float* As  = sm;                 // [f][i] i in 0..255
    float* Bs  = As + K2_AS;         // [f][j] j in 0..63
    float* Ds  = Bs + K2_BS;         // [i][65]
    float* sqs = Ds + K2_DS;         // [64]

    const int bb = blockIdx.x >> 4;
    const int rb = blockIdx.x & 15;
    const int n0 = rb * 256;
    const int tid = threadIdx.x;
    const int tx = tid & 7;          // col group (8 cols each)
    const int ty = tid >> 3;         // row group (rows ty + 32u)

    const float* xb = x + (size_t)bb * FIN * NPTS;

    // load query tile As[f][i]
    for (int idx = tid; idx < K2_AS; idx += 256) {
        int f = idx >> 8, i = idx & 255;
        As[idx] = xb[f * NPTS + n0 + i];
    }

    // per-thread top-k state (all accesses fully unrolled -> registers)
    float bestd[KNN];
    int   besti[KNN];
#pragma unroll
    for (int i = 0; i < KNN; ++i) { bestd[i] = 3.0e38f; besti[i] = 0; }
    float worst = 3.0e38f;
    const int nrow = n0 + tid;

    __syncthreads();

    for (int m0 = 0; m0 < NPTS; m0 += 64) {
        __syncthreads();  // prior Ds reads & Bs reads done

        // load candidate tile Bs[f][j] and sq norms
        for (int idx = tid; idx < 1024; idx += 256) {
            int f = idx >> 4, q = idx & 15;
            float4 v = *(const float4*)(xb + f * NPTS + m0 + q * 4);
            *(float4*)(Bs + f * 64 + q * 4) = v;
        }
        if (tid < 64) sqs[tid] = g_sq[bb * NPTS + m0 + tid];
        __syncthreads();

        // GEMM: each thread computes 8 rows x 8 cols (4 f32x2 col-pairs)
        unsigned long long acc[32];
#pragma unroll
        for (int i = 0; i < 32; ++i) acc[i] = 0ULL;

#pragma unroll 4
        for (int f = 0; f < 64; ++f) {
            unsigned long long a2[8];
#pragma unroll
            for (int u = 0; u < 8; ++u) {
                float a = As[f * 256 + ty + 32 * u];
                asm("mov.b64 %0, {%1, %1};" : "=l"(a2[u]) : "f"(a));
            }
            unsigned long long b2[4];
#pragma unroll
            for (int p = 0; p < 4; ++p)
                b2[p] = *(const unsigned long long*)(Bs + f * 64 + tx * 8 + 2 * p);
#pragma unroll
            for (int u = 0; u < 8; ++u)
#pragma unroll
                for (int p = 0; p < 4; ++p)
                    asm("fma.rn.f32x2 %0, %1, %2, %0;"
                        : "+l"(acc[u * 4 + p]) : "l"(a2[u]), "l"(b2[p]));
        }

        // stage dot tile to smem (padded stride 65 -> conflict-free)
#pragma unroll
        for (int u = 0; u < 8; ++u) {
            int r = ty + 32 * u;
#pragma unroll
            for (int p = 0; p < 4; ++p) {
                float lo, hi;
                asm("mov.b64 {%0, %1}, %2;" : "=f"(lo), "=f"(hi) : "l"(acc[u * 4 + p]));
                Ds[r * 65 + tx * 8 + 2 * p]     = lo;
                Ds[r * 65 + tx * 8 + 2 * p + 1] = hi;
            }
        }
        __syncthreads();

        // streaming top-k update: thread tid owns row tid
        const float* drow = Ds + tid * 65;
#pragma unroll 1
        for (int j = 0; j < 64; ++j) {
            float key = fmaf(-2.0f, drow[j], sqs[j]);
            int m = m0 + j;
            if (key < worst && m != nrow) {
                bool done = false;
                float nw = -3.0e38f;
#pragma unroll
                for (int i = 0; i < KNN; ++i) {
                    if (!done && bestd[i] == worst) {
                        bestd[i] = key; besti[i] = m; done = true;
                    }
                    if (bestd[i] > nw) nw = bestd[i];
                }
                worst = nw;
            }
        }
    }

    // write neighbor indices
    size_t base = ((size_t)(bb * NPTS + nrow)) * KNN;
#pragma unroll
    for (int i = 0; i < KNN; ++i) g_idx[base + i] = besti[i];
}

// ---------------------------------------------------------------------------
// Kernel 3: gather-max epilogue + transpose to [b][o][n]
// grid (64, 8), 256 threads; block handles 64 points
// ---------------------------------------------------------------------------
__global__ __launch_bounds__(256) void k3_epilogue(float* __restrict__ out)
{
    __shared__ float outs[64][65];
    const int bb  = blockIdx.y;
    const int n0  = blockIdx.x * 64;
    const int tid = threadIdx.x;
    const int w    = tid >> 5;
    const int lane = tid & 31;

    const float* Y = g_Yt + (size_t)bb * NPTS * 64;
    const float* C = g_Ct + (size_t)bb * NPTS * 64;

#pragma unroll 1
    for (int s = 0; s < 8; ++s) {
        int nn = w * 8 + s;
        int n  = n0 + nn;
        int jj = 0;
        if (lane < KNN) jj = g_idx[((size_t)(bb * NPTS + n)) * KNN + lane];
        float m0v = -3.0e38f, m1v = -3.0e38f;
#pragma unroll
        for (int i = 0; i < KNN; ++i) {
            int j = __shfl_sync(0xffffffffu, jj, i);
            const float* yr = Y + (size_t)j * 64;
            m0v = fmaxf(m0v, yr[lane]);
            m1v = fmaxf(m1v, yr[lane + 32]);
        }
        outs[nn][lane]      = m0v + C[(size_t)n * 64 + lane];
        outs[nn][lane + 32] = m1v + C[(size_t)n * 64 + lane + 32];
    }
    __syncthreads();

    float* ob = out + (size_t)bb * FOUT * NPTS;
#pragma unroll
    for (int it = 0; it < 16; ++it) {
        int lin = it * 256 + tid;
        int o  = lin >> 6;
        int nn = lin & 63;
        ob[o * NPTS + n0 + nn] = outs[nn][o];
    }
}

// ---------------------------------------------------------------------------
extern "C" void kernel_launch(void* const* d_in, const int* in_sizes, int n_in,
                              void* d_out, int out_size)
{
    const float* x    = (const float*)d_in[0];
    const float* W    = (const float*)d_in[1];
    const float* bvec = (const float*)d_in[2];
    float* out        = (float*)d_out;

    cudaFuncSetAttribute(k2_knn, cudaFuncAttributeMaxDynamicSharedMemorySize,
                         K2_SMEM_BYTES);

    k1_features<<<dim3(NPTS / 128, BATCH), 128>>>(x, W, bvec);
    k2_knn<<<BATCH * (NPTS / 256), 256, K2_SMEM_BYTES>>>(x);
    k3_epilogue<<<dim3(NPTS / 64, BATCH), 256>>>(out);
}